// round 8
// baseline (speedup 1.0000x reference)
#include <cuda_runtime.h>
#include <math.h>

// Problem constants
#define NB        4
#define SEQN      2048
#define DMODEL    256
#define HEADS     4
#define HD        64
#define ROWS_HALF 8192      // NB * SEQN
#define ROWS_TOT  16384     // 2 * NB * SEQN

// ---------------- scratch (no allocs allowed) ----------------
__device__ float g_qk[2 * NB * HEADS * SEQN * HD];  // [t][b][h][n][hd]
__device__ float g_v [2 * NB * HEADS * SEQN * HD];  // [t][b][h][n][hd]
__device__ float g_m [ROWS_TOT * DMODEL];           // attention out, head-merged
__device__ float g_mo[ROWS_TOT * DMODEL];           // after Wout
__device__ float g_y [ROWS_TOT * 512];              // after W0 / LN / gelu

// ---------------- shared SGEMM core helpers ----------------
// Tile: BM=128, BN=128, BK=16, 256 threads, 8x8 per thread.
// Double-buffered smem; loads staged through registers so LDG latency
// overlaps the previous tile's FMA work.

struct FragA { float4 a0, a1; };
struct FragB { float4 b0, b1; };

__device__ __forceinline__ FragA ldg_a_reg(const float* src, int ac) {
    FragA f;
    f.a0 = *(const float4*)(src + ac);
    f.a1 = *(const float4*)(src + ac + 4);
    return f;
}

__device__ __forceinline__ void sts_a(float (*As)[128], const FragA& f, int ar, int ac) {
    As[ac + 0][ar] = f.a0.x; As[ac + 1][ar] = f.a0.y;
    As[ac + 2][ar] = f.a0.z; As[ac + 3][ar] = f.a0.w;
    As[ac + 4][ar] = f.a1.x; As[ac + 5][ar] = f.a1.y;
    As[ac + 6][ar] = f.a1.z; As[ac + 7][ar] = f.a1.w;
}

__device__ __forceinline__ FragB ldg_b_reg(const float* B, int ldb, int k0, int n0, int tid) {
    FragB f;
    int br0 = tid >> 5;
    int bc  = (tid & 31) << 2;
    f.b0 = *(const float4*)(B + (size_t)(k0 + br0) * ldb + n0 + bc);
    f.b1 = *(const float4*)(B + (size_t)(k0 + br0 + 8) * ldb + n0 + bc);
    return f;
}

__device__ __forceinline__ void sts_b(float (*Bs)[128], const FragB& f, int tid) {
    int br0 = tid >> 5;
    int bc  = (tid & 31) << 2;
    *(float4*)&Bs[br0][bc]     = f.b0;
    *(float4*)&Bs[br0 + 8][bc] = f.b1;
}

__device__ __forceinline__ void mm_tile(const float (*As)[128], const float (*Bs)[128],
                                        float acc[8][8], int tx, int ty) {
#pragma unroll
    for (int k = 0; k < 16; ++k) {
        float a[8], b[8];
        *(float4*)&a[0] = *(const float4*)&As[k][ty * 8];
        *(float4*)&a[4] = *(const float4*)&As[k][ty * 8 + 4];
        *(float4*)&b[0] = *(const float4*)&Bs[k][tx * 8];
        *(float4*)&b[4] = *(const float4*)&Bs[k][tx * 8 + 4];
#pragma unroll
        for (int i = 0; i < 8; ++i)
#pragma unroll
            for (int j = 0; j < 8; ++j)
                acc[i][j] = fmaf(a[i], b[j], acc[i][j]);
    }
}

// ---------------- kernel 1: fused qk / v projection ----------------
// C = X @ [Wqk | Wv] + [bqk | bv], scattered into head-major layout.
__global__ __launch_bounds__(256) void k_proj(const float* __restrict__ x0,
                                              const float* __restrict__ x1,
                                              const float* __restrict__ Wqk,
                                              const float* __restrict__ bqk,
                                              const float* __restrict__ Wv,
                                              const float* __restrict__ bv) {
    __shared__ float As[2][16][128];
    __shared__ float Bs[2][16][128];
    int tid = threadIdx.x;
    int m0 = blockIdx.y * 128;
    int n0 = blockIdx.x * 128;            // 0..511
    bool isv = (n0 >= 256);
    const float* Bsrc = isv ? Wv : Wqk;
    const float* bias = isv ? bv : bqk;
    int bn0 = isv ? n0 - 256 : n0;        // 0 or 128

    int ar = tid >> 1, ac = (tid & 1) * 8;
    int r = m0 + ar;
    const float* arow = (r < ROWS_HALF) ? (x0 + (size_t)r * DMODEL)
                                        : (x1 + (size_t)(r - ROWS_HALF) * DMODEL);
    int tx = tid & 15, ty = tid >> 4;
    float acc[8][8] = {};

    // prologue
    {
        FragA fa = ldg_a_reg(arow, ac);
        FragB fb = ldg_b_reg(Bsrc, 256, 0, bn0, tid);
        sts_a(As[0], fa, ar, ac);
        sts_b(Bs[0], fb, tid);
    }
    __syncthreads();

    for (int k0 = 0; k0 < 256; k0 += 16) {
        int cur = (k0 >> 4) & 1;
        FragA fa; FragB fb;
        bool more = (k0 + 16 < 256);
        if (more) {
            fa = ldg_a_reg(arow + k0 + 16, ac);
            fb = ldg_b_reg(Bsrc, 256, k0 + 16, bn0, tid);
        }
        mm_tile(As[cur], Bs[cur], acc, tx, ty);
        if (more) {
            sts_a(As[cur ^ 1], fa, ar, ac);
            sts_b(Bs[cur ^ 1], fb, tid);
        }
        __syncthreads();
    }

    float* dst = isv ? g_v : g_qk;
#pragma unroll
    for (int i = 0; i < 8; ++i) {
        int r2 = m0 + ty * 8 + i;
        int t = (r2 >= ROWS_HALF);
        int rr = t ? r2 - ROWS_HALF : r2;
        int b  = rr / SEQN;
        int n  = rr % SEQN;
#pragma unroll
        for (int j = 0; j < 8; j += 4) {
            int c = bn0 + tx * 8 + j;     // column within the 256-wide matrix
            int h = c >> 6, hd = c & 63;  // 8-col chunk never crosses a head boundary
            float4 o;
            o.x = acc[i][j + 0] + bias[c + 0];
            o.y = acc[i][j + 1] + bias[c + 1];
            o.z = acc[i][j + 2] + bias[c + 2];
            o.w = acc[i][j + 3] + bias[c + 3];
            size_t di = ((((size_t)t * NB + b) * HEADS + h) * SEQN + n) * HD + hd;
            *(float4*)&dst[di] = o;
        }
    }
}

// ---------------- kernel 2: flash attention (both directions) ----------------
// dir=0: Q=qk0, K=qk1, V=v1 -> m0 rows [0, 8192)
// dir=1: Q=qk1, K=qk0, V=v0 -> m1 rows [8192, 16384)
__global__ __launch_bounds__(256) void k_attn() {
    int qt  = blockIdx.x;          // query tile: 0..31
    int bh  = blockIdx.y;          // 0..15
    int dir = blockIdx.z;          // 0..1
    int b = bh >> 2, h = bh & 3;
    int kv = 1 - dir;

    const float* Qbase = g_qk + (((size_t)dir * NB + b) * HEADS + h) * (size_t)SEQN * HD;
    const float* Kbase = g_qk + (((size_t)kv  * NB + b) * HEADS + h) * (size_t)SEQN * HD;
    const float* Vbase = g_v  + (((size_t)kv  * NB + b) * HEADS + h) * (size_t)SEQN * HD;

    __shared__ float Qs[64][64];   // d-major, XOR-swizzled: elem (d,q) at Qs[d][q ^ (d&60)]
    __shared__ float KPs[64][64];  // K: d-major swizzled; later P: [q][k] natural
    __shared__ float Vs[64][64];   // [k][d] natural

    int tid = threadIdx.x;
    int tx = tid & 15, ty = tid >> 4;
    const float scale = 0.125f;    // 1/sqrt(64)

    // Load + transpose Q once (scale folded in)
    for (int i = tid; i < 1024; i += 256) {
        int q  = i >> 4;
        int d4 = (i & 15) << 2;
        float4 v = *(const float4*)(Qbase + (size_t)(qt * 64 + q) * HD + d4);
        int c = q ^ d4;            // (d4+j)&60 == d4 for j<4
        Qs[d4 + 0][c] = v.x * scale;
        Qs[d4 + 1][c] = v.y * scale;
        Qs[d4 + 2][c] = v.z * scale;
        Qs[d4 + 3][c] = v.w * scale;
    }

    float O[4][4] = {};
    float rmax[4] = {-1e30f, -1e30f, -1e30f, -1e30f};
    float rsum[4] = {};

    for (int kt = 0; kt < 32; ++kt) {
        __syncthreads();  // previous PV done reading KPs/Vs (also orders Q store at kt=0)
        for (int i = tid; i < 1024; i += 256) {
            int kr = i >> 4;
            int d4 = (i & 15) << 2;
            const float* src = Kbase + (size_t)(kt * 64 + kr) * HD + d4;
            float4 v = *(const float4*)src;
            int c = kr ^ d4;
            KPs[d4 + 0][c] = v.x; KPs[d4 + 1][c] = v.y;
            KPs[d4 + 2][c] = v.z; KPs[d4 + 3][c] = v.w;
            float4 w = *(const float4*)(Vbase + (size_t)(kt * 64 + kr) * HD + d4);
            *(float4*)&Vs[kr][d4] = w;
        }
        __syncthreads();

        // S = (Q*scale) @ K^T  -> 4x4 fragment per thread
        float s[4][4] = {};
#pragma unroll 16
        for (int d = 0; d < 64; ++d) {
            int swz = d & 60;
            float4 qv = *(const float4*)&Qs[d][(ty * 4) ^ swz];
            float4 kv4 = *(const float4*)&KPs[d][(tx * 4) ^ swz];
            float qa[4] = {qv.x, qv.y, qv.z, qv.w};
            float ka[4] = {kv4.x, kv4.y, kv4.z, kv4.w};
#pragma unroll
            for (int i = 0; i < 4; ++i)
#pragma unroll
                for (int j = 0; j < 4; ++j)
                    s[i][j] = fmaf(qa[i], ka[j], s[i][j]);
        }

        // online softmax (row stats reduced over the 16 tx lanes sharing a ty)
#pragma unroll
        for (int qi = 0; qi < 4; ++qi) {
            float tm = fmaxf(fmaxf(s[qi][0], s[qi][1]), fmaxf(s[qi][2], s[qi][3]));
#pragma unroll
            for (int off = 8; off; off >>= 1)
                tm = fmaxf(tm, __shfl_xor_sync(0xffffffffu, tm, off));
            float nm   = fmaxf(rmax[qi], tm);
            float corr = __expf(rmax[qi] - nm);
            rmax[qi]   = nm;
            float ls = 0.f;
#pragma unroll
            for (int j = 0; j < 4; ++j) {
                float p = __expf(s[qi][j] - nm);
                s[qi][j] = p;
                ls += p;
            }
#pragma unroll
            for (int off = 8; off; off >>= 1)
                ls += __shfl_xor_sync(0xffffffffu, ls, off);
            rsum[qi] = rsum[qi] * corr + ls;
#pragma unroll
            for (int j = 0; j < 4; ++j) O[qi][j] *= corr;
        }

        __syncthreads();  // everyone done reading K from KPs
#pragma unroll
        for (int qi = 0; qi < 4; ++qi)
            *(float4*)&KPs[ty * 4 + qi][tx * 4] =
                make_float4(s[qi][0], s[qi][1], s[qi][2], s[qi][3]);
        __syncthreads();  // P ready

        // O += P @ V, kk blocked by 4: P fragments loaded as float4 (1 LDS.128
        // per qi per 4 kk instead of 4 scalar LDS per kk) -> LDS instr count
        // in this loop drops 5/kk -> 2/kk; FMA becomes the binding pipe.
#pragma unroll 4
        for (int kk = 0; kk < 64; kk += 4) {
            float pr[4][4];
#pragma unroll
            for (int qi = 0; qi < 4; ++qi) {
                float4 pv = *(const float4*)&KPs[ty * 4 + qi][kk];
                pr[qi][0] = pv.x; pr[qi][1] = pv.y;
                pr[qi][2] = pv.z; pr[qi][3] = pv.w;
            }
#pragma unroll
            for (int j = 0; j < 4; ++j) {
                float4 vv = *(const float4*)&Vs[kk + j][tx * 4];
#pragma unroll
                for (int qi = 0; qi < 4; ++qi) {
                    float p = pr[qi][j];
                    O[qi][0] = fmaf(p, vv.x, O[qi][0]);
                    O[qi][1] = fmaf(p, vv.y, O[qi][1]);
                    O[qi][2] = fmaf(p, vv.z, O[qi][2]);
                    O[qi][3] = fmaf(p, vv.w, O[qi][3]);
                }
            }
        }
    }

    size_t rowbase = (size_t)dir * ROWS_HALF + (size_t)b * SEQN + qt * 64;
#pragma unroll
    for (int qi = 0; qi < 4; ++qi) {
        float inv = 1.0f / rsum[qi];
        float4 o = make_float4(O[qi][0] * inv, O[qi][1] * inv,
                               O[qi][2] * inv, O[qi][3] * inv);
        size_t row = rowbase + ty * 4 + qi;
        *(float4*)&g_m[row * DMODEL + h * HD + tx * 4] = o;
    }
}

// ---------------- kernel 3: mo = m @ Wout + bout ----------------
__global__ __launch_bounds__(256) void k_outproj(const float* __restrict__ Wout,
                                                 const float* __restrict__ bout) {
    __shared__ float As[2][16][128];
    __shared__ float Bs[2][16][128];
    int tid = threadIdx.x;
    int m0 = blockIdx.y * 128;
    int n0 = blockIdx.x * 128;
    int ar = tid >> 1, ac = (tid & 1) * 8;
    const float* arow = g_m + (size_t)(m0 + ar) * DMODEL;
    int tx = tid & 15, ty = tid >> 4;
    float acc[8][8] = {};

    {
        FragA fa = ldg_a_reg(arow, ac);
        FragB fb = ldg_b_reg(Wout, 256, 0, n0, tid);
        sts_a(As[0], fa, ar, ac);
        sts_b(Bs[0], fb, tid);
    }
    __syncthreads();

    for (int k0 = 0; k0 < 256; k0 += 16) {
        int cur = (k0 >> 4) & 1;
        FragA fa; FragB fb;
        bool more = (k0 + 16 < 256);
        if (more) {
            fa = ldg_a_reg(arow + k0 + 16, ac);
            fb = ldg_b_reg(Wout, 256, k0 + 16, n0, tid);
        }
        mm_tile(As[cur], Bs[cur], acc, tx, ty);
        if (more) {
            sts_a(As[cur ^ 1], fa, ar, ac);
            sts_b(Bs[cur ^ 1], fb, tid);
        }
        __syncthreads();
    }
#pragma unroll
    for (int i = 0; i < 8; ++i) {
        float* orow = g_mo + (size_t)(m0 + ty * 8 + i) * DMODEL + n0 + tx * 8;
#pragma unroll
        for (int j = 0; j < 8; j += 4) {
            int c = n0 + tx * 8 + j;
            float4 o;
            o.x = acc[i][j + 0] + bout[c + 0];
            o.y = acc[i][j + 1] + bout[c + 1];
            o.z = acc[i][j + 2] + bout[c + 2];
            o.w = acc[i][j + 3] + bout[c + 3];
            *(float4*)(orow + j) = o;
        }
    }
}

// ---------------- kernel 4: y = [x | mo] @ W0 + b0 ----------------
__global__ __launch_bounds__(256) void k_ffn0(const float* __restrict__ x0,
                                              const float* __restrict__ x1,
                                              const float* __restrict__ W0,
                                              const float* __restrict__ b0) {
    __shared__ float As[2][16][128];
    __shared__ float Bs[2][16][128];
    int tid = threadIdx.x;
    int m0 = blockIdx.y * 128;
    int n0 = blockIdx.x * 128;   // 0..511
    int ar = tid >> 1, ac = (tid & 1) * 8;
    int r = m0 + ar;
    const float* ax = (r < ROWS_HALF) ? (x0 + (size_t)r * DMODEL)
                                      : (x1 + (size_t)(r - ROWS_HALF) * DMODEL);
    const float* am = g_mo + (size_t)r * DMODEL;
    int tx = tid & 15, ty = tid >> 4;
    float acc[8][8] = {};

    {
        FragA fa = ldg_a_reg(ax, ac);
        FragB fb = ldg_b_reg(W0, 512, 0, n0, tid);
        sts_a(As[0], fa, ar, ac);
        sts_b(Bs[0], fb, tid);
    }
    __syncthreads();

    for (int k0 = 0; k0 < 512; k0 += 16) {
        int cur = (k0 >> 4) & 1;
        FragA fa; FragB fb;
        bool more = (k0 + 16 < 512);
        if (more) {
            int kn = k0 + 16;
            const float* anext = (kn < 256) ? (ax + kn) : (am + (kn - 256));
            fa = ldg_a_reg(anext, ac);
            fb = ldg_b_reg(W0, 512, kn, n0, tid);
        }
        mm_tile(As[cur], Bs[cur], acc, tx, ty);
        if (more) {
            sts_a(As[cur ^ 1], fa, ar, ac);
            sts_b(Bs[cur ^ 1], fb, tid);
        }
        __syncthreads();
    }
#pragma unroll
    for (int i = 0; i < 8; ++i) {
        float* orow = g_y + (size_t)(m0 + ty * 8 + i) * 512 + n0 + tx * 8;
#pragma unroll
        for (int j = 0; j < 8; j += 4) {
            int c = n0 + tx * 8 + j;
            float4 o;
            o.x = acc[i][j + 0] + b0[c + 0];
            o.y = acc[i][j + 1] + b0[c + 1];
            o.z = acc[i][j + 2] + b0[c + 2];
            o.w = acc[i][j + 3] + b0[c + 3];
            *(float4*)(orow + j) = o;
        }
    }
}

// ---------------- kernel 5: layernorm + exact gelu (in place on g_y) ----------------
__global__ __launch_bounds__(128) void k_lngelu(const float* __restrict__ lns,
                                                const float* __restrict__ lnb) {
    __shared__ float red[4];
    int row = blockIdx.x;
    int t = threadIdx.x;
    float* yp = g_y + (size_t)row * 512 + t * 4;
    float4 v = *(float4*)yp;

    float s = v.x + v.y + v.z + v.w;
#pragma unroll
    for (int off = 16; off; off >>= 1) s += __shfl_xor_sync(0xffffffffu, s, off);
    if ((t & 31) == 0) red[t >> 5] = s;
    __syncthreads();
    float mean = (red[0] + red[1] + red[2] + red[3]) * (1.0f / 512.0f);

    float d0 = v.x - mean, d1 = v.y - mean, d2 = v.z - mean, d3 = v.w - mean;
    float ss = d0 * d0 + d1 * d1 + d2 * d2 + d3 * d3;
#pragma unroll
    for (int off = 16; off; off >>= 1) ss += __shfl_xor_sync(0xffffffffu, ss, off);
    __syncthreads();
    if ((t & 31) == 0) red[t >> 5] = ss;
    __syncthreads();
    float var = (red[0] + red[1] + red[2] + red[3]) * (1.0f / 512.0f);
    float rstd = rsqrtf(var + 1e-5f);

    int c = t * 4;
    float g0 = d0 * rstd * lns[c + 0] + lnb[c + 0];
    float g1 = d1 * rstd * lns[c + 1] + lnb[c + 1];
    float g2 = d2 * rstd * lns[c + 2] + lnb[c + 2];
    float g3 = d3 * rstd * lns[c + 3] + lnb[c + 3];
    const float is2 = 0.70710678118654752f;
    v.x = 0.5f * g0 * (1.0f + erff(g0 * is2));
    v.y = 0.5f * g1 * (1.0f + erff(g1 * is2));
    v.z = 0.5f * g2 * (1.0f + erff(g2 * is2));
    v.w = 0.5f * g3 * (1.0f + erff(g3 * is2));
    *(float4*)yp = v;
}

// ---------------- kernel 6: out = x + y @ W3 + b3 ----------------
__global__ __launch_bounds__(256) void k_ffn3(const float* __restrict__ x0,
                                              const float* __restrict__ x1,
                                              const float* __restrict__ W3,
                                              const float* __restrict__ b3,
                                              float* __restrict__ out) {
    __shared__ float As[2][16][128];
    __shared__ float Bs[2][16][128];
    int tid = threadIdx.x;
    int m0 = blockIdx.y * 128;
    int n0 = blockIdx.x * 128;   // 0..255
    int ar = tid >> 1, ac = (tid & 1) * 8;
    const float* arow = g_y + (size_t)(m0 + ar) * 512;
    int tx = tid & 15, ty = tid >> 4;
    float acc[8][8] = {};

    {
        FragA fa = ldg_a_reg(arow, ac);
        FragB fb = ldg_b_reg(W3, 256, 0, n0, tid);
        sts_a(As[0], fa, ar, ac);
        sts_b(Bs[0], fb, tid);
    }
    __syncthreads();

    for (int k0 = 0; k0 < 512; k0 += 16) {
        int cur = (k0 >> 4) & 1;
        FragA fa; FragB fb;
        bool more = (k0 + 16 < 512);
        if (more) {
            fa = ldg_a_reg(arow + k0 + 16, ac);
            fb = ldg_b_reg(W3, 256, k0 + 16, n0, tid);
        }
        mm_tile(As[cur], Bs[cur], acc, tx, ty);
        if (more) {
            sts_a(As[cur ^ 1], fa, ar, ac);
            sts_b(Bs[cur ^ 1], fb, tid);
        }
        __syncthreads();
    }
#pragma unroll
    for (int i = 0; i < 8; ++i) {
        int r2 = m0 + ty * 8 + i;
        const float* xrow = (r2 < ROWS_HALF) ? (x0 + (size_t)r2 * DMODEL)
                                             : (x1 + (size_t)(r2 - ROWS_HALF) * DMODEL);
        float* orow = out + (size_t)r2 * DMODEL + n0 + tx * 8;
#pragma unroll
        for (int j = 0; j < 8; j += 4) {
            int c = n0 + tx * 8 + j;
            float4 xv = *(const float4*)(xrow + c);
            float4 o;
            o.x = acc[i][j + 0] + b3[c + 0] + xv.x;
            o.y = acc[i][j + 1] + b3[c + 1] + xv.y;
            o.z = acc[i][j + 2] + b3[c + 2] + xv.z;
            o.w = acc[i][j + 3] + b3[c + 3] + xv.w;
            *(float4*)(orow + j) = o;
        }
    }
}

// ---------------- launch ----------------
extern "C" void kernel_launch(void* const* d_in, const int* in_sizes, int n_in,
                              void* d_out, int out_size) {
    const float* x0   = (const float*)d_in[0];
    const float* x1   = (const float*)d_in[1];
    const float* Wqk  = (const float*)d_in[2];
    const float* bqk  = (const float*)d_in[3];
    const float* Wv   = (const float*)d_in[4];
    const float* bv   = (const float*)d_in[5];
    const float* Wout = (const float*)d_in[6];
    const float* bout = (const float*)d_in[7];
    const float* W0   = (const float*)d_in[8];
    const float* b0   = (const float*)d_in[9];
    const float* lns  = (const float*)d_in[10];
    const float* lnb  = (const float*)d_in[11];
    const float* W3   = (const float*)d_in[12];
    const float* b3   = (const float*)d_in[13];
    float* out = (float*)d_out;

    k_proj   <<<dim3(4, 128), 256>>>(x0, x1, Wqk, bqk, Wv, bv);
    k_attn   <<<dim3(32, 16, 2), 256>>>();
    k_outproj<<<dim3(2, 128), 256>>>(Wout, bout);
    k_ffn0   <<<dim3(4, 128), 256>>>(x0, x1, W0, b0);
    k_lngelu <<<ROWS_TOT, 128>>>(lns, lnb);
    k_ffn3   <<<dim3(2, 128), 256>>>(x0, x1, W3, b3, out);
}